// round 15
// baseline (speedup 1.0000x reference)
#include <cuda_runtime.h>
#include <cuda_fp16.h>
#include <cstdint>
#include <math.h>

// ---------------- problem constants ----------------
#define TOKENS 4096          // B*S = 2*2048
#define SEQ    2048
#define BATCH  2
#define DMODEL 1024
#define D3     3072
#define FFN    4096
#define NHEAD  16
#define HDIM   64

// ---------------- fp32 scratch ----------------
__device__ float g_attnout[TOKENS * (size_t)DMODEL];
__device__ float g_h1     [TOKENS * (size_t)DMODEL];
__device__ float g_ffn2   [TOKENS * (size_t)DMODEL];

// ---------------- fp16 scratch ----------------
__device__ __half g_xh   [TOKENS * (size_t)DMODEL];
__device__ __half g_wqt_h[(size_t)D3 * DMODEL];     // [N][K]
__device__ __half g_wot_h[(size_t)DMODEL * DMODEL];
__device__ __half g_w1t_h[(size_t)FFN * DMODEL];
__device__ __half g_w2t_h[(size_t)DMODEL * FFN];
__device__ __half g_attnh[TOKENS * (size_t)DMODEL];
__device__ __half g_h1h  [TOKENS * (size_t)DMODEL];
__device__ __half g_fhh  [TOKENS * (size_t)FFN];

// ---------------- per-head planar fp16 QKV ----------
// layout: [bh][seq][64]
__device__ __half g_qph[(size_t)BATCH * NHEAD * SEQ * HDIM];
__device__ __half g_kph[(size_t)BATCH * NHEAD * SEQ * HDIM];
__device__ __half g_vph[(size_t)BATCH * NHEAD * SEQ * HDIM];

// =====================================================================
// helpers
// =====================================================================
__device__ __forceinline__ uint32_t smem_u32(const void* p) {
    uint32_t a;
    asm("{ .reg .u64 t; cvta.to.shared.u64 t, %1; cvt.u32.u64 %0, t; }"
        : "=r"(a) : "l"(p));
    return a;
}

__device__ __forceinline__ void ldm_x4(uint32_t* r, uint32_t addr) {
    asm volatile("ldmatrix.sync.aligned.m8n8.x4.shared.b16 {%0,%1,%2,%3}, [%4];"
                 : "=r"(r[0]), "=r"(r[1]), "=r"(r[2]), "=r"(r[3]) : "r"(addr));
}

__device__ __forceinline__ void ldm_x4t(uint32_t* r, uint32_t addr) {
    asm volatile("ldmatrix.sync.aligned.m8n8.x4.trans.shared.b16 {%0,%1,%2,%3}, [%4];"
                 : "=r"(r[0]), "=r"(r[1]), "=r"(r[2]), "=r"(r[3]) : "r"(addr));
}

// fp32-accumulate MMA (attention keeps this)
__device__ __forceinline__ void mma_f16(float* d, const uint32_t* a,
                                        uint32_t b0, uint32_t b1) {
    asm volatile(
        "mma.sync.aligned.m16n8k16.row.col.f32.f16.f16.f32 "
        "{%0,%1,%2,%3},{%4,%5,%6,%7},{%8,%9},{%0,%1,%2,%3};"
        : "+f"(d[0]), "+f"(d[1]), "+f"(d[2]), "+f"(d[3])
        : "r"(a[0]), "r"(a[1]), "r"(a[2]), "r"(a[3]), "r"(b0), "r"(b1));
}

// fp16-accumulate MMA with C=0; result spilled to fp32 by caller
__device__ __forceinline__ void mma_f16a(uint32_t* d, const uint32_t* a,
                                         uint32_t b0, uint32_t b1) {
    asm volatile(
        "mma.sync.aligned.m16n8k16.row.col.f16.f16.f16.f16 "
        "{%0,%1},{%2,%3,%4,%5},{%6,%7},{%8,%9};"
        : "=r"(d[0]), "=r"(d[1])
        : "r"(a[0]), "r"(a[1]), "r"(a[2]), "r"(a[3]),
          "r"(b0), "r"(b1), "r"(0u), "r"(0u));
}

__device__ __forceinline__ uint32_t packh2(float a, float b) {
    __half2 h = __floats2half2_rn(a, b);
    return *reinterpret_cast<uint32_t*>(&h);
}

__device__ __forceinline__ void cp16(uint32_t dst, const void* src) {
    asm volatile("cp.async.cg.shared.global [%0], [%1], 16;"
                 :: "r"(dst), "l"(src));
}
#define CP_COMMIT() asm volatile("cp.async.commit_group;" ::: "memory")
#define CP_WAIT0()  asm volatile("cp.async.wait_group 0;" ::: "memory")

// fused QKV epilogue writer: (row, col pair) of qkv fp32 -> planar fp16
__device__ __forceinline__ void qkv_write(
    __half* __restrict__ qh, __half* __restrict__ kh, __half* __restrict__ vh,
    int row, int col, float x, float y)
{
    const int h    = col / 192;
    const int r2   = col - h * 192;
    const int part = r2 >> 6;            // 0=q 1=k 2=v
    const int d    = r2 & 63;            // even (col pairs are even)
    const int b    = row >> 11, s = row & 2047;
    const size_t po = ((size_t)(b * NHEAD + h) * SEQ + s) * HDIM + d;
    if (part == 0) {
        *(uint32_t*)(qh + po) = packh2(x * 0.125f, y * 0.125f);
    } else if (part == 1) {
        *(uint32_t*)(kh + po) = packh2(x, y);
    } else {
        *(uint32_t*)(vh + po) = packh2(x, y);
    }
}

// =====================================================================
// convert kernels (run once per launch; memory-bound)
// =====================================================================
__global__ __launch_bounds__(256)
void conv_plain(const float* __restrict__ src, __half* __restrict__ dh)
{
    const int idx = blockIdx.x * 256 + threadIdx.x;     // float4 index
    float4 v = ((const float4*)src)[idx];
    ((uint2*)dh)[idx] = make_uint2(packh2(v.x, v.y), packh2(v.z, v.w));
}

// W[K][N] -> Th[N][K] (fp16-rn), half2 stores (4B transactions)
__global__ __launch_bounds__(256)
void conv_transpose(const float* __restrict__ W,
                    __half* __restrict__ Th, int K, int N)
{
    __shared__ float t[32][33];
    const int bn = blockIdx.x * 32, bk = blockIdx.y * 32;
    const int tx = threadIdx.x & 31, ty = threadIdx.x >> 5;   // 32 x 8
    #pragma unroll
    for (int j = 0; j < 32; j += 8)
        t[ty + j][tx] = W[(size_t)(bk + ty + j) * N + bn + tx];
    __syncthreads();
    // write phase: thread handles k-pairs -> half2 store
    const int u  = threadIdx.x & 15;          // k-pair 0..15
    const int n0 = threadIdx.x >> 4;          // 0..15
    #pragma unroll
    for (int j = 0; j < 2; ++j) {
        const int n = n0 + j * 16;
        const float v0 = t[2 * u][n];
        const float v1 = t[2 * u + 1][n];
        *(uint32_t*)(Th + (size_t)(bn + n) * K + bk + 2 * u) = packh2(v0, v1);
    }
}

// =====================================================================
// HMMA GEMM, fp16 operands, f16-ACC MMAs (C=0) spilled per-k16 into
// fp32 register accumulators.  C = A @ B^T + bias.
// A: [M][K] fp16.  B: [N][K] fp16.
// CTA 128x128, BK=64 (2x 32-k sub-tiles), 8 warps (warp tile 64x32),
// cp.async double buffer, 2 CTAs/SM.
// MODE: 0 = fp32 out, 1 = relu + fp16 out, 2 = fused QKV planar out.
// =====================================================================
#define STRB   80                     // bytes per smem row (32 fp16 + pad)
#define TILE32 (128 * STRB)           // 10240 B per 128x32 tile
#define BUF_B  (4 * TILE32)           // A0, A1, B0, B1 = 40960 B
#define GEMM_SMEM (2 * BUF_B)         // 81920 B

template<int MODE>
__global__ __launch_bounds__(256, 2)
void gemm_f16(const __half* __restrict__ Ah,
              const __half* __restrict__ Bh,
              const float* __restrict__ bias,
              float* __restrict__ C,
              __half* __restrict__ Ch,
              __half* __restrict__ qh, __half* __restrict__ kh,
              __half* __restrict__ vh,
              int M, int N, int K)
{
    extern __shared__ char smraw[];
    const uint32_t sb = smem_u32(smraw);
    const int tid = threadIdx.x;
    const int l   = tid & 31, w = tid >> 5;
    const int bm  = blockIdx.y * 128, bn = blockIdx.x * 128;
    const int wm  = (w & 1) << 6;
    const int wn  = (w >> 1) << 5;

    const int la = l & 15;
    const int lk = (l >> 4) << 3;
    const int T  = K >> 6;

    float acc[4][4][4];
    #pragma unroll
    for (int i = 0; i < 4; ++i)
        #pragma unroll
        for (int j = 0; j < 4; ++j)
            #pragma unroll
            for (int q = 0; q < 4; ++q) acc[i][j][q] = 0.f;

    auto issue_tile = [&](int t) {
        const int k0 = t << 6;
        const uint32_t base = sb + (t & 1) * BUF_B;
        #pragma unroll
        for (int s32 = 0; s32 < 2; ++s32)
            #pragma unroll
            for (int i = 0; i < 2; ++i) {
                const int c   = tid + (i << 8);     // 0..511
                const int row = c >> 2, kc = c & 3;
                const uint32_t doff = (uint32_t)(row * STRB + kc * 16);
                const int kg = k0 + s32 * 32 + kc * 8;
                cp16(base + s32 * TILE32 + doff,
                     Ah + (size_t)(bm + row) * K + kg);
                cp16(base + 2 * TILE32 + s32 * TILE32 + doff,
                     Bh + (size_t)(bn + row) * K + kg);
            }
        CP_COMMIT();
    };

    auto compute = [&](int bsel) {
        const uint32_t base0 = sb + bsel * BUF_B;
        #pragma unroll
        for (int s32 = 0; s32 < 2; ++s32) {
            const uint32_t baseA = base0 + s32 * TILE32;
            const uint32_t baseB = base0 + 2 * TILE32 + s32 * TILE32;
            #pragma unroll
            for (int ks = 0; ks < 2; ++ks) {
                uint32_t ah[4][4], bh[2][4];
                #pragma unroll
                for (int mf = 0; mf < 4; ++mf) {
                    uint32_t off = (uint32_t)((wm + mf * 16 + la) * STRB +
                                              (ks * 16 + lk) * 2);
                    ldm_x4(ah[mf], baseA + off);
                }
                #pragma unroll
                for (int nf2 = 0; nf2 < 2; ++nf2) {
                    uint32_t off = (uint32_t)((wn + nf2 * 16 + la) * STRB +
                                              (ks * 16 + lk) * 2);
                    ldm_x4(bh[nf2], baseB + off);
                }
                #pragma unroll
                for (int mf = 0; mf < 4; ++mf)
                    #pragma unroll
                    for (int nf = 0; nf < 4; ++nf) {
                        const int g = nf >> 1, s = nf & 1;
                        uint32_t d[2];
                        mma_f16a(d, ah[mf], bh[g][s], bh[g][2 + s]);
                        float2 p0 = __half22float2(*reinterpret_cast<__half2*>(&d[0]));
                        float2 p1 = __half22float2(*reinterpret_cast<__half2*>(&d[1]));
                        acc[mf][nf][0] += p0.x;
                        acc[mf][nf][1] += p0.y;
                        acc[mf][nf][2] += p1.x;
                        acc[mf][nf][3] += p1.y;
                    }
            }
        }
    };

    issue_tile(0);
    for (int t = 0; t < T; ++t) {
        CP_WAIT0();
        __syncthreads();
        if (t + 1 < T) issue_tile(t + 1);
        compute(t & 1);
        __syncthreads();
    }

    const int g  = l >> 2;
    const int tg = (l & 3) << 1;
    #pragma unroll
    for (int mf = 0; mf < 4; ++mf) {
        const int r0 = bm + wm + mf * 16 + g;
        #pragma unroll
        for (int nf = 0; nf < 4; ++nf) {
            const int c = bn + wn + nf * 8 + tg;
            float2 bv = *(const float2*)&bias[c];
            float v0 = acc[mf][nf][0] + bv.x;
            float v1 = acc[mf][nf][1] + bv.y;
            float v2 = acc[mf][nf][2] + bv.x;
            float v3 = acc[mf][nf][3] + bv.y;
            if (MODE == 1) {
                v0 = fmaxf(v0, 0.f); v1 = fmaxf(v1, 0.f);
                v2 = fmaxf(v2, 0.f); v3 = fmaxf(v3, 0.f);
                *(uint32_t*)((char*)Ch + ((size_t)r0 * N + c) * 2)       = packh2(v0, v1);
                *(uint32_t*)((char*)Ch + ((size_t)(r0 + 8) * N + c) * 2) = packh2(v2, v3);
            } else if (MODE == 2) {
                qkv_write(qh, kh, vh, r0,     c, v0, v1);
                qkv_write(qh, kh, vh, r0 + 8, c, v2, v3);
            } else {
                *(float2*)&C[(size_t)r0 * N + c]       = make_float2(v0, v1);
                *(float2*)&C[(size_t)(r0 + 8) * N + c] = make_float2(v2, v3);
            }
        }
    }
}

// =====================================================================
// MMA flash attention, pure fp16 operands (f32 accum — unchanged).
// grid (16 qtiles, 32 bh), 256 threads (8 warps), warp = 16 q-rows.
// =====================================================================
#define A_STR   72                         // halves per smem row (64 + 8 pad)
#define A_TILE  (128 * A_STR)              // 9216 halves per tile
#define A_QH    0
#define A_BUF0  A_TILE                     // 9216
#define A_BUFSZ (2 * A_TILE)               // Kh, Vh = 18432 halves
#define A_KH    0
#define A_VH    A_TILE
#define ATTN_SMEM ((A_BUF0 + 2 * A_BUFSZ) * 2)   // 92160 bytes

__global__ __launch_bounds__(256, 1)
void attention_mma(const __half* __restrict__ qh_g,
                   const __half* __restrict__ kh_g, const __half* __restrict__ vh_g,
                   __half* __restrict__ outh)
{
    extern __shared__ char smraw[];
    const uint32_t sb = smem_u32(smraw);
    const int tid = threadIdx.x;
    const int l   = tid & 31, w = tid >> 5;
    const int qt  = blockIdx.x;
    const int bh  = blockIdx.y;
    const int b   = bh >> 4, h = bh & 15;

    const size_t plane = (size_t)bh * SEQ * HDIM;
    const int la  = l & 15;
    const int lk8 = (l >> 4) << 3;
    const int qrow0 = w << 4;

    auto load_tile = [&](const __half* src, uint32_t dsth, int row0) {
        #pragma unroll
        for (int i = 0; i < 4; ++i) {
            const int c   = tid + (i << 8);        // 0..1023
            const int row = c >> 3, c8 = (c & 7) << 3;
            cp16(sb + (dsth + row * A_STR + c8) * 2,
                 src + plane + (size_t)(row0 + row) * HDIM + c8);
        }
    };

    load_tile(qh_g, A_QH, qt * 128);
    load_tile(kh_g, A_BUF0 + A_KH, 0);
    load_tile(vh_g, A_BUF0 + A_VH, 0);
    CP_COMMIT();

    float oacc[8][4];
    #pragma unroll
    for (int i = 0; i < 8; ++i)
        #pragma unroll
        for (int j = 0; j < 4; ++j) oacc[i][j] = 0.f;
    float mrow0 = -1e30f, mrow1 = -1e30f, lrow0 = 0.f, lrow1 = 0.f;

    for (int kt = 0; kt < SEQ / 128; ++kt) {
        CP_WAIT0();
        __syncthreads();
        if (kt + 1 < SEQ / 128) {
            const uint32_t nb = A_BUF0 + ((kt + 1) & 1) * A_BUFSZ;
            load_tile(kh_g, nb + A_KH, (kt + 1) * 128);
            load_tile(vh_g, nb + A_VH, (kt + 1) * 128);
            CP_COMMIT();
        }
        const uint32_t kb_base = sb + (A_BUF0 + (kt & 1) * A_BUFSZ) * 2;

        float sacc[16][4];
        #pragma unroll
        for (int i = 0; i < 16; ++i)
            #pragma unroll
            for (int j = 0; j < 4; ++j) sacc[i][j] = 0.f;

        #pragma unroll
        for (int ks = 0; ks < 4; ++ks) {
            const uint32_t qoff = (uint32_t)((qrow0 + la) * A_STR + ks * 16 + lk8) * 2;
            uint32_t qhf[4];
            ldm_x4(qhf, sb + A_QH * 2 + qoff);
            uint32_t kb[8][4];
            #pragma unroll
            for (int g2 = 0; g2 < 8; ++g2)
                ldm_x4(kb[g2], kb_base +
                       (uint32_t)(((g2 << 4) + la) * A_STR + ks * 16 + lk8) * 2);
            #pragma unroll
            for (int nf = 0; nf < 16; ++nf) {
                const int g2 = nf >> 1, s = nf & 1;
                mma_f16(sacc[nf], qhf, kb[g2][s], kb[g2][2 + s]);
            }
        }

        float tm0 = -1e30f, tm1 = -1e30f;
        #pragma unroll
        for (int nf = 0; nf < 16; ++nf) {
            tm0 = fmaxf(tm0, fmaxf(sacc[nf][0], sacc[nf][1]));
            tm1 = fmaxf(tm1, fmaxf(sacc[nf][2], sacc[nf][3]));
        }
        tm0 = fmaxf(tm0, __shfl_xor_sync(0xffffffffu, tm0, 1));
        tm0 = fmaxf(tm0, __shfl_xor_sync(0xffffffffu, tm0, 2));
        tm1 = fmaxf(tm1, __shfl_xor_sync(0xffffffffu, tm1, 1));
        tm1 = fmaxf(tm1, __shfl_xor_sync(0xffffffffu, tm1, 2));
        const float m0n = fmaxf(mrow0, tm0), m1n = fmaxf(mrow1, tm1);
        const float c0 = __expf(mrow0 - m0n), c1 = __expf(mrow1 - m1n);
        float rs0 = 0.f, rs1 = 0.f;
        #pragma unroll
        for (int nf = 0; nf < 16; ++nf) {
            sacc[nf][0] = __expf(sacc[nf][0] - m0n);
            sacc[nf][1] = __expf(sacc[nf][1] - m0n);
            sacc[nf][2] = __expf(sacc[nf][2] - m1n);
            sacc[nf][3] = __expf(sacc[nf][3] - m1n);
            rs0 += sacc[nf][0] + sacc[nf][1];
            rs1 += sacc[nf][2] + sacc[nf][3];
        }
        rs0 += __shfl_xor_sync(0xffffffffu, rs0, 1);
        rs0 += __shfl_xor_sync(0xffffffffu, rs0, 2);
        rs1 += __shfl_xor_sync(0xffffffffu, rs1, 1);
        rs1 += __shfl_xor_sync(0xffffffffu, rs1, 2);
        lrow0 = lrow0 * c0 + rs0;  mrow0 = m0n;
        lrow1 = lrow1 * c1 + rs1;  mrow1 = m1n;
        #pragma unroll
        for (int nf = 0; nf < 8; ++nf) {
            oacc[nf][0] *= c0; oacc[nf][1] *= c0;
            oacc[nf][2] *= c1; oacc[nf][3] *= c1;
        }

        #pragma unroll
        for (int ks2 = 0; ks2 < 8; ++ks2) {
            uint32_t aP[4];
            aP[0] = packh2(sacc[2 * ks2][0],     sacc[2 * ks2][1]);
            aP[1] = packh2(sacc[2 * ks2][2],     sacc[2 * ks2][3]);
            aP[2] = packh2(sacc[2 * ks2 + 1][0], sacc[2 * ks2 + 1][1]);
            aP[3] = packh2(sacc[2 * ks2 + 1][2], sacc[2 * ks2 + 1][3]);
            #pragma unroll
            for (int nb = 0; nb < 4; ++nb) {
                const uint32_t voff =
                    (uint32_t)(((ks2 << 4) + la) * A_STR + (nb << 4) + lk8) * 2;
                uint32_t vbh[4];
                ldm_x4t(vbh, kb_base + A_VH * 2 + voff);
                mma_f16(oacc[2 * nb],     aP, vbh[0], vbh[1]);
                mma_f16(oacc[2 * nb + 1], aP, vbh[2], vbh[3]);
            }
        }
    }

    const int g  = l >> 2;
    const int tq = (l & 3) << 1;
    const float inv0 = 1.f / lrow0, inv1 = 1.f / lrow1;
    const size_t tok0 = (size_t)b * SEQ + qt * 128 + qrow0 + g;
    #pragma unroll
    for (int nf = 0; nf < 8; ++nf) {
        const int col = h * HDIM + nf * 8 + tq;
        *(uint32_t*)((char*)outh + (tok0 * DMODEL + col) * 2) =
            packh2(oacc[nf][0] * inv0, oacc[nf][1] * inv0);
        *(uint32_t*)((char*)outh + ((tok0 + 8) * DMODEL + col) * 2) =
            packh2(oacc[nf][2] * inv1, oacc[nf][3] * inv1);
    }
}

// =====================================================================
// Fused residual add + LayerNorm; optionally emits fp16 too.
// =====================================================================
template<bool EMIT>
__global__ __launch_bounds__(256)
void add_ln_kernel(const float* __restrict__ a, const float* __restrict__ res,
                   const float* __restrict__ gamma, const float* __restrict__ beta,
                   float* __restrict__ out,
                   __half* __restrict__ outh)
{
    __shared__ float ss[8], qq[8];
    const int row = blockIdx.x;
    const int tid = threadIdx.x;
    const size_t base = (size_t)row * DMODEL + tid * 4;

    float4 va = *(const float4*)&a[base];
    float4 vr = *(const float4*)&res[base];
    float x0 = va.x + vr.x, x1 = va.y + vr.y, x2 = va.z + vr.z, x3 = va.w + vr.w;

    float s = x0 + x1 + x2 + x3;
    float q = x0 * x0 + x1 * x1 + x2 * x2 + x3 * x3;
    #pragma unroll
    for (int off = 16; off > 0; off >>= 1) {
        s += __shfl_xor_sync(0xffffffffu, s, off);
        q += __shfl_xor_sync(0xffffffffu, q, off);
    }
    const int w = tid >> 5;
    if ((tid & 31) == 0) { ss[w] = s; qq[w] = q; }
    __syncthreads();
    if (tid < 32) {
        float s2 = (tid < 8) ? ss[tid] : 0.f;
        float q2 = (tid < 8) ? qq[tid] : 0.f;
        #pragma unroll
        for (int off = 4; off > 0; off >>= 1) {
            s2 += __shfl_xor_sync(0xffffffffu, s2, off);
            q2 += __shfl_xor_sync(0xffffffffu, q2, off);
        }
        if (tid == 0) { ss[0] = s2; qq[0] = q2; }
    }
    __syncthreads();

    const float mean = ss[0] * (1.f / DMODEL);
    const float var  = qq[0] * (1.f / DMODEL) - mean * mean;
    const float rstd = rsqrtf(var + 1e-5f);

    float4 g  = *(const float4*)&gamma[tid * 4];
    float4 bt = *(const float4*)&beta[tid * 4];
    float4 ov;
    ov.x = (x0 - mean) * rstd * g.x + bt.x;
    ov.y = (x1 - mean) * rstd * g.y + bt.y;
    ov.z = (x2 - mean) * rstd * g.z + bt.z;
    ov.w = (x3 - mean) * rstd * g.w + bt.w;
    *(float4*)&out[base] = ov;

    if (EMIT) {
        *(uint2*)((char*)outh + base * 2) =
            make_uint2(packh2(ov.x, ov.y), packh2(ov.z, ov.w));
    }
}

// =====================================================================
// kernel_launch
// =====================================================================
extern "C" void kernel_launch(void* const* d_in, const int* in_sizes, int n_in,
                              void* d_out, int out_size)
{
    const float* x      = (const float*)d_in[0];
    const float* W_qkv  = (const float*)d_in[1];
    const float* b_qkv  = (const float*)d_in[2];
    const float* W_o    = (const float*)d_in[3];
    const float* b_o    = (const float*)d_in[4];
    const float* gamma1 = (const float*)d_in[5];
    const float* beta1  = (const float*)d_in[6];
    const float* W1     = (const float*)d_in[7];
    const float* b1     = (const float*)d_in[8];
    const float* W2     = (const float*)d_in[9];
    const float* b2     = (const float*)d_in[10];
    const float* gamma2 = (const float*)d_in[11];
    const float* beta2  = (const float*)d_in[12];
    float* out = (float*)d_out;

    float *attnout, *h1, *ffn2;
    cudaGetSymbolAddress((void**)&attnout, g_attnout);
    cudaGetSymbolAddress((void**)&h1,      g_h1);
    cudaGetSymbolAddress((void**)&ffn2,    g_ffn2);

    __half *xh, *wqh, *woh, *w1h, *w2h;
    __half *ath, *h1h, *fhh;
    __half *qph, *kph, *vph;
    cudaGetSymbolAddress((void**)&xh,  g_xh);
    cudaGetSymbolAddress((void**)&wqh, g_wqt_h);
    cudaGetSymbolAddress((void**)&woh, g_wot_h);
    cudaGetSymbolAddress((void**)&w1h, g_w1t_h);
    cudaGetSymbolAddress((void**)&w2h, g_w2t_h);
    cudaGetSymbolAddress((void**)&ath, g_attnh);
    cudaGetSymbolAddress((void**)&h1h, g_h1h);
    cudaGetSymbolAddress((void**)&fhh, g_fhh);
    cudaGetSymbolAddress((void**)&qph, g_qph);
    cudaGetSymbolAddress((void**)&kph, g_kph);
    cudaGetSymbolAddress((void**)&vph, g_vph);

    cudaFuncSetAttribute(attention_mma,
                         cudaFuncAttributeMaxDynamicSharedMemorySize, ATTN_SMEM);
    cudaFuncSetAttribute(gemm_f16<0>,
                         cudaFuncAttributeMaxDynamicSharedMemorySize, GEMM_SMEM);
    cudaFuncSetAttribute(gemm_f16<1>,
                         cudaFuncAttributeMaxDynamicSharedMemorySize, GEMM_SMEM);
    cudaFuncSetAttribute(gemm_f16<2>,
                         cudaFuncAttributeMaxDynamicSharedMemorySize, GEMM_SMEM);

    dim3 blk(256);

    // ---- one-time converts ----
    conv_plain<<<(TOKENS * DMODEL) / (256 * 4), blk>>>(x, xh);
    conv_transpose<<<dim3(D3 / 32,    DMODEL / 32), blk>>>(W_qkv, wqh, DMODEL, D3);
    conv_transpose<<<dim3(DMODEL / 32, DMODEL / 32), blk>>>(W_o,  woh, DMODEL, DMODEL);
    conv_transpose<<<dim3(FFN / 32,   DMODEL / 32), blk>>>(W1,   w1h, DMODEL, FFN);
    conv_transpose<<<dim3(DMODEL / 32, FFN / 32),   blk>>>(W2,   w2h, FFN, DMODEL);

    // 1) qkv GEMM with fused planar-QKV epilogue       [4096, 3072]
    gemm_f16<2><<<dim3(D3 / 128, TOKENS / 128), blk, GEMM_SMEM>>>(
        xh, wqh, b_qkv, nullptr, nullptr,
        qph, kph, vph, TOKENS, D3, DMODEL);

    // 2) MMA flash attention -> fp16                   [4096, 1024]
    attention_mma<<<dim3(SEQ / 128, BATCH * NHEAD), blk, ATTN_SMEM>>>(
        qph, kph, vph, ath);

    // 3) attn_out = attn @ W_o + b_o                   [4096, 1024]
    gemm_f16<0><<<dim3(DMODEL / 128, TOKENS / 128), blk, GEMM_SMEM>>>(
        ath, woh, b_o, attnout, nullptr,
        nullptr, nullptr, nullptr, TOKENS, DMODEL, DMODEL);

    // 4) h1 = LN(attn_out + x)  (+ fp16)
    add_ln_kernel<true><<<TOKENS, blk>>>(attnout, x, gamma1, beta1, h1, h1h);

    // 5) ffnh = relu(h1 @ W1 + b1) -> fp16             [4096, 4096]
    gemm_f16<1><<<dim3(FFN / 128, TOKENS / 128), blk, GEMM_SMEM>>>(
        h1h, w1h, b1, nullptr, fhh,
        nullptr, nullptr, nullptr, TOKENS, FFN, DMODEL);

    // 6) ffn2 = ffnh @ W2 + b2                         [4096, 1024]
    gemm_f16<0><<<dim3(DMODEL / 128, TOKENS / 128), blk, GEMM_SMEM>>>(
        fhh, w2h, b2, ffn2, nullptr,
        nullptr, nullptr, nullptr, TOKENS, DMODEL, FFN);

    // 7) out = LN(ffn2 + h1)
    add_ln_kernel<false><<<TOKENS, blk>>>(ffn2, h1, gamma2, beta2, out, nullptr);
}

// round 16
// speedup vs baseline: 1.3119x; 1.3119x over previous
#include <cuda_runtime.h>
#include <cuda_fp16.h>
#include <cstdint>
#include <math.h>

// ---------------- problem constants ----------------
#define TOKENS 4096          // B*S = 2*2048
#define SEQ    2048
#define BATCH  2
#define DMODEL 1024
#define D3     3072
#define FFN    4096
#define NHEAD  16
#define HDIM   64

// ---------------- fp32 scratch ----------------
__device__ float g_attnout[TOKENS * (size_t)DMODEL];
__device__ float g_h1     [TOKENS * (size_t)DMODEL];
__device__ float g_ffn2   [TOKENS * (size_t)DMODEL];

// ---------------- fp16 scratch ----------------
__device__ __half g_xh   [TOKENS * (size_t)DMODEL];
__device__ __half g_wqt_h[(size_t)D3 * DMODEL];     // [N][K]
__device__ __half g_wot_h[(size_t)DMODEL * DMODEL];
__device__ __half g_w1t_h[(size_t)FFN * DMODEL];
__device__ __half g_w2t_h[(size_t)DMODEL * FFN];
__device__ __half g_attnh[TOKENS * (size_t)DMODEL];
__device__ __half g_h1h  [TOKENS * (size_t)DMODEL];
__device__ __half g_fhh  [TOKENS * (size_t)FFN];

// ---------------- per-head planar fp16 QKV ----------
// layout: [bh][seq][64]
__device__ __half g_qph[(size_t)BATCH * NHEAD * SEQ * HDIM];
__device__ __half g_kph[(size_t)BATCH * NHEAD * SEQ * HDIM];
__device__ __half g_vph[(size_t)BATCH * NHEAD * SEQ * HDIM];

// =====================================================================
// helpers
// =====================================================================
__device__ __forceinline__ uint32_t smem_u32(const void* p) {
    uint32_t a;
    asm("{ .reg .u64 t; cvta.to.shared.u64 t, %1; cvt.u32.u64 %0, t; }"
        : "=r"(a) : "l"(p));
    return a;
}

__device__ __forceinline__ void ldm_x4(uint32_t* r, uint32_t addr) {
    asm volatile("ldmatrix.sync.aligned.m8n8.x4.shared.b16 {%0,%1,%2,%3}, [%4];"
                 : "=r"(r[0]), "=r"(r[1]), "=r"(r[2]), "=r"(r[3]) : "r"(addr));
}

__device__ __forceinline__ void ldm_x4t(uint32_t* r, uint32_t addr) {
    asm volatile("ldmatrix.sync.aligned.m8n8.x4.trans.shared.b16 {%0,%1,%2,%3}, [%4];"
                 : "=r"(r[0]), "=r"(r[1]), "=r"(r[2]), "=r"(r[3]) : "r"(addr));
}

// fp32-accumulate MMA (proven fastest on sm_103 classic path)
__device__ __forceinline__ void mma_f16(float* d, const uint32_t* a,
                                        uint32_t b0, uint32_t b1) {
    asm volatile(
        "mma.sync.aligned.m16n8k16.row.col.f32.f16.f16.f32 "
        "{%0,%1,%2,%3},{%4,%5,%6,%7},{%8,%9},{%0,%1,%2,%3};"
        : "+f"(d[0]), "+f"(d[1]), "+f"(d[2]), "+f"(d[3])
        : "r"(a[0]), "r"(a[1]), "r"(a[2]), "r"(a[3]), "r"(b0), "r"(b1));
}

__device__ __forceinline__ uint32_t packh2(float a, float b) {
    __half2 h = __floats2half2_rn(a, b);
    return *reinterpret_cast<uint32_t*>(&h);
}

__device__ __forceinline__ void cp16(uint32_t dst, const void* src) {
    asm volatile("cp.async.cg.shared.global [%0], [%1], 16;"
                 :: "r"(dst), "l"(src));
}
#define CP_COMMIT() asm volatile("cp.async.commit_group;" ::: "memory")
#define CP_WAIT0()  asm volatile("cp.async.wait_group 0;" ::: "memory")

// fused QKV epilogue writer: (row, col pair) of qkv fp32 -> planar fp16
__device__ __forceinline__ void qkv_write(
    __half* __restrict__ qh, __half* __restrict__ kh, __half* __restrict__ vh,
    int row, int col, float x, float y)
{
    const int h    = col / 192;
    const int r2   = col - h * 192;
    const int part = r2 >> 6;            // 0=q 1=k 2=v
    const int d    = r2 & 63;            // even (col pairs are even)
    const int b    = row >> 11, s = row & 2047;
    const size_t po = ((size_t)(b * NHEAD + h) * SEQ + s) * HDIM + d;
    if (part == 0) {
        *(uint32_t*)(qh + po) = packh2(x * 0.125f, y * 0.125f);
    } else if (part == 1) {
        *(uint32_t*)(kh + po) = packh2(x, y);
    } else {
        *(uint32_t*)(vh + po) = packh2(x, y);
    }
}

// =====================================================================
// convert kernels (run once per launch; memory-bound)
// =====================================================================
__global__ __launch_bounds__(256)
void conv_plain(const float* __restrict__ src, __half* __restrict__ dh)
{
    const int idx = blockIdx.x * 256 + threadIdx.x;     // float4 index
    float4 v = ((const float4*)src)[idx];
    ((uint2*)dh)[idx] = make_uint2(packh2(v.x, v.y), packh2(v.z, v.w));
}

// Batched weight transpose+convert: all four W[K][N] -> Th[N][K] in ONE
// launch.  Flat blockIdx.x is dispatched across the four weights.
// Tile counts: wq 96x32=3072, wo 32x32=1024, w1 128x32=4096, w2 32x128=4096.
#define CT_WQ_END 3072
#define CT_WO_END (CT_WQ_END + 1024)
#define CT_W1_END (CT_WO_END + 4096)
#define CT_TOTAL  (CT_W1_END + 4096)

__global__ __launch_bounds__(256)
void conv_transpose_all(const float* __restrict__ Wq, __half* __restrict__ Tq,
                        const float* __restrict__ Wo, __half* __restrict__ To,
                        const float* __restrict__ W1, __half* __restrict__ T1,
                        const float* __restrict__ W2, __half* __restrict__ T2)
{
    const float* W; __half* Th; int K, N, bid;
    if (blockIdx.x < CT_WQ_END)      { W = Wq; Th = Tq; K = DMODEL; N = D3;
                                       bid = blockIdx.x; }
    else if (blockIdx.x < CT_WO_END) { W = Wo; Th = To; K = DMODEL; N = DMODEL;
                                       bid = blockIdx.x - CT_WQ_END; }
    else if (blockIdx.x < CT_W1_END) { W = W1; Th = T1; K = DMODEL; N = FFN;
                                       bid = blockIdx.x - CT_WO_END; }
    else                             { W = W2; Th = T2; K = FFN;    N = DMODEL;
                                       bid = blockIdx.x - CT_W1_END; }
    const int ntx = N >> 5;                    // tiles along N
    const int bn  = (bid % ntx) * 32;
    const int bk  = (bid / ntx) * 32;

    __shared__ float t[32][33];
    const int tx = threadIdx.x & 31, ty = threadIdx.x >> 5;   // 32 x 8
    #pragma unroll
    for (int j = 0; j < 32; j += 8)
        t[ty + j][tx] = W[(size_t)(bk + ty + j) * N + bn + tx];
    __syncthreads();
    // write phase: thread handles k-pairs -> half2 store
    const int u  = threadIdx.x & 15;          // k-pair 0..15
    const int n0 = threadIdx.x >> 4;          // 0..15
    #pragma unroll
    for (int j = 0; j < 2; ++j) {
        const int n = n0 + j * 16;
        const float v0 = t[2 * u][n];
        const float v1 = t[2 * u + 1][n];
        *(uint32_t*)(Th + (size_t)(bn + n) * K + bk + 2 * u) = packh2(v0, v1);
    }
}

// =====================================================================
// HMMA GEMM, pure fp16, f32 accumulate (proven R14 config):
// C = A @ B^T + bias.   A: [M][K] fp16.  B: [N][K] fp16.
// CTA 128x128, BK=64 (2x 32-k sub-tiles), 8 warps (warp tile 64x32),
// cp.async double buffer, 2 CTAs/SM.
// MODE: 0 = fp32 out, 1 = relu + fp16 out, 2 = fused QKV planar out.
// =====================================================================
#define STRB   80                     // bytes per smem row (32 fp16 + pad)
#define TILE32 (128 * STRB)           // 10240 B per 128x32 tile
#define BUF_B  (4 * TILE32)           // A0, A1, B0, B1 = 40960 B
#define GEMM_SMEM (2 * BUF_B)         // 81920 B

template<int MODE>
__global__ __launch_bounds__(256, 2)
void gemm_f16(const __half* __restrict__ Ah,
              const __half* __restrict__ Bh,
              const float* __restrict__ bias,
              float* __restrict__ C,
              __half* __restrict__ Ch,
              __half* __restrict__ qh, __half* __restrict__ kh,
              __half* __restrict__ vh,
              int M, int N, int K)
{
    extern __shared__ char smraw[];
    const uint32_t sb = smem_u32(smraw);
    const int tid = threadIdx.x;
    const int l   = tid & 31, w = tid >> 5;
    const int bm  = blockIdx.y * 128, bn = blockIdx.x * 128;
    const int wm  = (w & 1) << 6;
    const int wn  = (w >> 1) << 5;

    const int la = l & 15;
    const int lk = (l >> 4) << 3;
    const int T  = K >> 6;

    float acc[4][4][4];
    #pragma unroll
    for (int i = 0; i < 4; ++i)
        #pragma unroll
        for (int j = 0; j < 4; ++j)
            #pragma unroll
            for (int q = 0; q < 4; ++q) acc[i][j][q] = 0.f;

    auto issue_tile = [&](int t) {
        const int k0 = t << 6;
        const uint32_t base = sb + (t & 1) * BUF_B;
        #pragma unroll
        for (int s32 = 0; s32 < 2; ++s32)
            #pragma unroll
            for (int i = 0; i < 2; ++i) {
                const int c   = tid + (i << 8);     // 0..511
                const int row = c >> 2, kc = c & 3;
                const uint32_t doff = (uint32_t)(row * STRB + kc * 16);
                const int kg = k0 + s32 * 32 + kc * 8;
                cp16(base + s32 * TILE32 + doff,
                     Ah + (size_t)(bm + row) * K + kg);
                cp16(base + 2 * TILE32 + s32 * TILE32 + doff,
                     Bh + (size_t)(bn + row) * K + kg);
            }
        CP_COMMIT();
    };

    auto compute = [&](int bsel) {
        const uint32_t base0 = sb + bsel * BUF_B;
        #pragma unroll
        for (int s32 = 0; s32 < 2; ++s32) {
            const uint32_t baseA = base0 + s32 * TILE32;
            const uint32_t baseB = base0 + 2 * TILE32 + s32 * TILE32;
            #pragma unroll
            for (int ks = 0; ks < 2; ++ks) {
                uint32_t ah[4][4], bh[2][4];
                #pragma unroll
                for (int mf = 0; mf < 4; ++mf) {
                    uint32_t off = (uint32_t)((wm + mf * 16 + la) * STRB +
                                              (ks * 16 + lk) * 2);
                    ldm_x4(ah[mf], baseA + off);
                }
                #pragma unroll
                for (int nf2 = 0; nf2 < 2; ++nf2) {
                    uint32_t off = (uint32_t)((wn + nf2 * 16 + la) * STRB +
                                              (ks * 16 + lk) * 2);
                    ldm_x4(bh[nf2], baseB + off);
                }
                #pragma unroll
                for (int mf = 0; mf < 4; ++mf)
                    #pragma unroll
                    for (int nf = 0; nf < 4; ++nf) {
                        const int g = nf >> 1, s = nf & 1;
                        mma_f16(acc[mf][nf], ah[mf], bh[g][s], bh[g][2 + s]);
                    }
            }
        }
    };

    issue_tile(0);
    for (int t = 0; t < T; ++t) {
        CP_WAIT0();
        __syncthreads();
        if (t + 1 < T) issue_tile(t + 1);
        compute(t & 1);
        __syncthreads();
    }

    const int g  = l >> 2;
    const int tg = (l & 3) << 1;
    #pragma unroll
    for (int mf = 0; mf < 4; ++mf) {
        const int r0 = bm + wm + mf * 16 + g;
        #pragma unroll
        for (int nf = 0; nf < 4; ++nf) {
            const int c = bn + wn + nf * 8 + tg;
            float2 bv = *(const float2*)&bias[c];
            float v0 = acc[mf][nf][0] + bv.x;
            float v1 = acc[mf][nf][1] + bv.y;
            float v2 = acc[mf][nf][2] + bv.x;
            float v3 = acc[mf][nf][3] + bv.y;
            if (MODE == 1) {
                v0 = fmaxf(v0, 0.f); v1 = fmaxf(v1, 0.f);
                v2 = fmaxf(v2, 0.f); v3 = fmaxf(v3, 0.f);
                *(uint32_t*)((char*)Ch + ((size_t)r0 * N + c) * 2)       = packh2(v0, v1);
                *(uint32_t*)((char*)Ch + ((size_t)(r0 + 8) * N + c) * 2) = packh2(v2, v3);
            } else if (MODE == 2) {
                qkv_write(qh, kh, vh, r0,     c, v0, v1);
                qkv_write(qh, kh, vh, r0 + 8, c, v2, v3);
            } else {
                *(float2*)&C[(size_t)r0 * N + c]       = make_float2(v0, v1);
                *(float2*)&C[(size_t)(r0 + 8) * N + c] = make_float2(v2, v3);
            }
        }
    }
}

// =====================================================================
// MMA flash attention, pure fp16 operands (f32 accum; proven R14).
// grid (16 qtiles, 32 bh), 256 threads (8 warps), warp = 16 q-rows.
// =====================================================================
#define A_STR   72                         // halves per smem row (64 + 8 pad)
#define A_TILE  (128 * A_STR)              // 9216 halves per tile
#define A_QH    0
#define A_BUF0  A_TILE                     // 9216
#define A_BUFSZ (2 * A_TILE)               // Kh, Vh = 18432 halves
#define A_KH    0
#define A_VH    A_TILE
#define ATTN_SMEM ((A_BUF0 + 2 * A_BUFSZ) * 2)   // 92160 bytes

__global__ __launch_bounds__(256, 1)
void attention_mma(const __half* __restrict__ qh_g,
                   const __half* __restrict__ kh_g, const __half* __restrict__ vh_g,
                   __half* __restrict__ outh)
{
    extern __shared__ char smraw[];
    const uint32_t sb = smem_u32(smraw);
    const int tid = threadIdx.x;
    const int l   = tid & 31, w = tid >> 5;
    const int qt  = blockIdx.x;
    const int bh  = blockIdx.y;
    const int b   = bh >> 4, h = bh & 15;

    const size_t plane = (size_t)bh * SEQ * HDIM;
    const int la  = l & 15;
    const int lk8 = (l >> 4) << 3;
    const int qrow0 = w << 4;

    auto load_tile = [&](const __half* src, uint32_t dsth, int row0) {
        #pragma unroll
        for (int i = 0; i < 4; ++i) {
            const int c   = tid + (i << 8);        // 0..1023
            const int row = c >> 3, c8 = (c & 7) << 3;
            cp16(sb + (dsth + row * A_STR + c8) * 2,
                 src + plane + (size_t)(row0 + row) * HDIM + c8);
        }
    };

    load_tile(qh_g, A_QH, qt * 128);
    load_tile(kh_g, A_BUF0 + A_KH, 0);
    load_tile(vh_g, A_BUF0 + A_VH, 0);
    CP_COMMIT();

    float oacc[8][4];
    #pragma unroll
    for (int i = 0; i < 8; ++i)
        #pragma unroll
        for (int j = 0; j < 4; ++j) oacc[i][j] = 0.f;
    float mrow0 = -1e30f, mrow1 = -1e30f, lrow0 = 0.f, lrow1 = 0.f;

    for (int kt = 0; kt < SEQ / 128; ++kt) {
        CP_WAIT0();
        __syncthreads();
        if (kt + 1 < SEQ / 128) {
            const uint32_t nb = A_BUF0 + ((kt + 1) & 1) * A_BUFSZ;
            load_tile(kh_g, nb + A_KH, (kt + 1) * 128);
            load_tile(vh_g, nb + A_VH, (kt + 1) * 128);
            CP_COMMIT();
        }
        const uint32_t kb_base = sb + (A_BUF0 + (kt & 1) * A_BUFSZ) * 2;

        float sacc[16][4];
        #pragma unroll
        for (int i = 0; i < 16; ++i)
            #pragma unroll
            for (int j = 0; j < 4; ++j) sacc[i][j] = 0.f;

        #pragma unroll
        for (int ks = 0; ks < 4; ++ks) {
            const uint32_t qoff = (uint32_t)((qrow0 + la) * A_STR + ks * 16 + lk8) * 2;
            uint32_t qhf[4];
            ldm_x4(qhf, sb + A_QH * 2 + qoff);
            uint32_t kb[8][4];
            #pragma unroll
            for (int g2 = 0; g2 < 8; ++g2)
                ldm_x4(kb[g2], kb_base +
                       (uint32_t)(((g2 << 4) + la) * A_STR + ks * 16 + lk8) * 2);
            #pragma unroll
            for (int nf = 0; nf < 16; ++nf) {
                const int g2 = nf >> 1, s = nf & 1;
                mma_f16(sacc[nf], qhf, kb[g2][s], kb[g2][2 + s]);
            }
        }

        float tm0 = -1e30f, tm1 = -1e30f;
        #pragma unroll
        for (int nf = 0; nf < 16; ++nf) {
            tm0 = fmaxf(tm0, fmaxf(sacc[nf][0], sacc[nf][1]));
            tm1 = fmaxf(tm1, fmaxf(sacc[nf][2], sacc[nf][3]));
        }
        tm0 = fmaxf(tm0, __shfl_xor_sync(0xffffffffu, tm0, 1));
        tm0 = fmaxf(tm0, __shfl_xor_sync(0xffffffffu, tm0, 2));
        tm1 = fmaxf(tm1, __shfl_xor_sync(0xffffffffu, tm1, 1));
        tm1 = fmaxf(tm1, __shfl_xor_sync(0xffffffffu, tm1, 2));
        const float m0n = fmaxf(mrow0, tm0), m1n = fmaxf(mrow1, tm1);
        const float c0 = __expf(mrow0 - m0n), c1 = __expf(mrow1 - m1n);
        float rs0 = 0.f, rs1 = 0.f;
        #pragma unroll
        for (int nf = 0; nf < 16; ++nf) {
            sacc[nf][0] = __expf(sacc[nf][0] - m0n);
            sacc[nf][1] = __expf(sacc[nf][1] - m0n);
            sacc[nf][2] = __expf(sacc[nf][2] - m1n);
            sacc[nf][3] = __expf(sacc[nf][3] - m1n);
            rs0 += sacc[nf][0] + sacc[nf][1];
            rs1 += sacc[nf][2] + sacc[nf][3];
        }
        rs0 += __shfl_xor_sync(0xffffffffu, rs0, 1);
        rs0 += __shfl_xor_sync(0xffffffffu, rs0, 2);
        rs1 += __shfl_xor_sync(0xffffffffu, rs1, 1);
        rs1 += __shfl_xor_sync(0xffffffffu, rs1, 2);
        lrow0 = lrow0 * c0 + rs0;  mrow0 = m0n;
        lrow1 = lrow1 * c1 + rs1;  mrow1 = m1n;
        #pragma unroll
        for (int nf = 0; nf < 8; ++nf) {
            oacc[nf][0] *= c0; oacc[nf][1] *= c0;
            oacc[nf][2] *= c1; oacc[nf][3] *= c1;
        }

        #pragma unroll
        for (int ks2 = 0; ks2 < 8; ++ks2) {
            uint32_t aP[4];
            aP[0] = packh2(sacc[2 * ks2][0],     sacc[2 * ks2][1]);
            aP[1] = packh2(sacc[2 * ks2][2],     sacc[2 * ks2][3]);
            aP[2] = packh2(sacc[2 * ks2 + 1][0], sacc[2 * ks2 + 1][1]);
            aP[3] = packh2(sacc[2 * ks2 + 1][2], sacc[2 * ks2 + 1][3]);
            #pragma unroll
            for (int nb = 0; nb < 4; ++nb) {
                const uint32_t voff =
                    (uint32_t)(((ks2 << 4) + la) * A_STR + (nb << 4) + lk8) * 2;
                uint32_t vbh[4];
                ldm_x4t(vbh, kb_base + A_VH * 2 + voff);
                mma_f16(oacc[2 * nb],     aP, vbh[0], vbh[1]);
                mma_f16(oacc[2 * nb + 1], aP, vbh[2], vbh[3]);
            }
        }
    }

    const int g  = l >> 2;
    const int tq = (l & 3) << 1;
    const float inv0 = 1.f / lrow0, inv1 = 1.f / lrow1;
    const size_t tok0 = (size_t)b * SEQ + qt * 128 + qrow0 + g;
    #pragma unroll
    for (int nf = 0; nf < 8; ++nf) {
        const int col = h * HDIM + nf * 8 + tq;
        *(uint32_t*)((char*)outh + (tok0 * DMODEL + col) * 2) =
            packh2(oacc[nf][0] * inv0, oacc[nf][1] * inv0);
        *(uint32_t*)((char*)outh + ((tok0 + 8) * DMODEL + col) * 2) =
            packh2(oacc[nf][2] * inv1, oacc[nf][3] * inv1);
    }
}

// =====================================================================
// Fused residual add + LayerNorm; optionally emits fp16 too.
// =====================================================================
template<bool EMIT>
__global__ __launch_bounds__(256)
void add_ln_kernel(const float* __restrict__ a, const float* __restrict__ res,
                   const float* __restrict__ gamma, const float* __restrict__ beta,
                   float* __restrict__ out,
                   __half* __restrict__ outh)
{
    __shared__ float ss[8], qq[8];
    const int row = blockIdx.x;
    const int tid = threadIdx.x;
    const size_t base = (size_t)row * DMODEL + tid * 4;

    float4 va = *(const float4*)&a[base];
    float4 vr = *(const float4*)&res[base];
    float x0 = va.x + vr.x, x1 = va.y + vr.y, x2 = va.z + vr.z, x3 = va.w + vr.w;

    float s = x0 + x1 + x2 + x3;
    float q = x0 * x0 + x1 * x1 + x2 * x2 + x3 * x3;
    #pragma unroll
    for (int off = 16; off > 0; off >>= 1) {
        s += __shfl_xor_sync(0xffffffffu, s, off);
        q += __shfl_xor_sync(0xffffffffu, q, off);
    }
    const int w = tid >> 5;
    if ((tid & 31) == 0) { ss[w] = s; qq[w] = q; }
    __syncthreads();
    if (tid < 32) {
        float s2 = (tid < 8) ? ss[tid] : 0.f;
        float q2 = (tid < 8) ? qq[tid] : 0.f;
        #pragma unroll
        for (int off = 4; off > 0; off >>= 1) {
            s2 += __shfl_xor_sync(0xffffffffu, s2, off);
            q2 += __shfl_xor_sync(0xffffffffu, q2, off);
        }
        if (tid == 0) { ss[0] = s2; qq[0] = q2; }
    }
    __syncthreads();

    const float mean = ss[0] * (1.f / DMODEL);
    const float var  = qq[0] * (1.f / DMODEL) - mean * mean;
    const float rstd = rsqrtf(var + 1e-5f);

    float4 g  = *(const float4*)&gamma[tid * 4];
    float4 bt = *(const float4*)&beta[tid * 4];
    float4 ov;
    ov.x = (x0 - mean) * rstd * g.x + bt.x;
    ov.y = (x1 - mean) * rstd * g.y + bt.y;
    ov.z = (x2 - mean) * rstd * g.z + bt.z;
    ov.w = (x3 - mean) * rstd * g.w + bt.w;
    *(float4*)&out[base] = ov;

    if (EMIT) {
        *(uint2*)((char*)outh + base * 2) =
            make_uint2(packh2(ov.x, ov.y), packh2(ov.z, ov.w));
    }
}

// =====================================================================
// kernel_launch
// =====================================================================
extern "C" void kernel_launch(void* const* d_in, const int* in_sizes, int n_in,
                              void* d_out, int out_size)
{
    const float* x      = (const float*)d_in[0];
    const float* W_qkv  = (const float*)d_in[1];
    const float* b_qkv  = (const float*)d_in[2];
    const float* W_o    = (const float*)d_in[3];
    const float* b_o    = (const float*)d_in[4];
    const float* gamma1 = (const float*)d_in[5];
    const float* beta1  = (const float*)d_in[6];
    const float* W1     = (const float*)d_in[7];
    const float* b1     = (const float*)d_in[8];
    const float* W2     = (const float*)d_in[9];
    const float* b2     = (const float*)d_in[10];
    const float* gamma2 = (const float*)d_in[11];
    const float* beta2  = (const float*)d_in[12];
    float* out = (float*)d_out;

    float *attnout, *h1, *ffn2;
    cudaGetSymbolAddress((void**)&attnout, g_attnout);
    cudaGetSymbolAddress((void**)&h1,      g_h1);
    cudaGetSymbolAddress((void**)&ffn2,    g_ffn2);

    __half *xh, *wqh, *woh, *w1h, *w2h;
    __half *ath, *h1h, *fhh;
    __half *qph, *kph, *vph;
    cudaGetSymbolAddress((void**)&xh,  g_xh);
    cudaGetSymbolAddress((void**)&wqh, g_wqt_h);
    cudaGetSymbolAddress((void**)&woh, g_wot_h);
    cudaGetSymbolAddress((void**)&w1h, g_w1t_h);
    cudaGetSymbolAddress((void**)&w2h, g_w2t_h);
    cudaGetSymbolAddress((void**)&ath, g_attnh);
    cudaGetSymbolAddress((void**)&h1h, g_h1h);
    cudaGetSymbolAddress((void**)&fhh, g_fhh);
    cudaGetSymbolAddress((void**)&qph, g_qph);
    cudaGetSymbolAddress((void**)&kph, g_kph);
    cudaGetSymbolAddress((void**)&vph, g_vph);

    cudaFuncSetAttribute(attention_mma,
                         cudaFuncAttributeMaxDynamicSharedMemorySize, ATTN_SMEM);
    cudaFuncSetAttribute(gemm_f16<0>,
                         cudaFuncAttributeMaxDynamicSharedMemorySize, GEMM_SMEM);
    cudaFuncSetAttribute(gemm_f16<1>,
                         cudaFuncAttributeMaxDynamicSharedMemorySize, GEMM_SMEM);
    cudaFuncSetAttribute(gemm_f16<2>,
                         cudaFuncAttributeMaxDynamicSharedMemorySize, GEMM_SMEM);

    dim3 blk(256);

    // ---- one-time converts (x + all four weights in one launch) ----
    conv_plain<<<(TOKENS * DMODEL) / (256 * 4), blk>>>(x, xh);
    conv_transpose_all<<<CT_TOTAL, blk>>>(W_qkv, wqh, W_o, woh,
                                          W1, w1h, W2, w2h);

    // 1) qkv GEMM with fused planar-QKV epilogue       [4096, 3072]
    gemm_f16<2><<<dim3(D3 / 128, TOKENS / 128), blk, GEMM_SMEM>>>(
        xh, wqh, b_qkv, nullptr, nullptr,
        qph, kph, vph, TOKENS, D3, DMODEL);

    // 2) MMA flash attention -> fp16                   [4096, 1024]
    attention_mma<<<dim3(SEQ / 128, BATCH * NHEAD), blk, ATTN_SMEM>>>(
        qph, kph, vph, ath);

    // 3) attn_out = attn @ W_o + b_o                   [4096, 1024]
    gemm_f16<0><<<dim3(DMODEL / 128, TOKENS / 128), blk, GEMM_SMEM>>>(
        ath, woh, b_o, attnout, nullptr,
        nullptr, nullptr, nullptr, TOKENS, DMODEL, DMODEL);

    // 4) h1 = LN(attn_out + x)  (+ fp16)
    add_ln_kernel<true><<<TOKENS, blk>>>(attnout, x, gamma1, beta1, h1, h1h);

    // 5) ffnh = relu(h1 @ W1 + b1) -> fp16             [4096, 4096]
    gemm_f16<1><<<dim3(FFN / 128, TOKENS / 128), blk, GEMM_SMEM>>>(
        h1h, w1h, b1, nullptr, fhh,
        nullptr, nullptr, nullptr, TOKENS, FFN, DMODEL);

    // 6) ffn2 = ffnh @ W2 + b2                         [4096, 1024]
    gemm_f16<0><<<dim3(DMODEL / 128, TOKENS / 128), blk, GEMM_SMEM>>>(
        fhh, w2h, b2, ffn2, nullptr,
        nullptr, nullptr, nullptr, TOKENS, DMODEL, FFN);

    // 7) out = LN(ffn2 + h1)
    add_ln_kernel<false><<<TOKENS, blk>>>(ffn2, h1, gamma2, beta2, out, nullptr);
}

// round 17
// speedup vs baseline: 1.3178x; 1.0045x over previous
#include <cuda_runtime.h>
#include <cuda_fp16.h>
#include <cstdint>
#include <math.h>

// ---------------- problem constants ----------------
#define TOKENS 4096          // B*S = 2*2048
#define SEQ    2048
#define BATCH  2
#define DMODEL 1024
#define D3     3072
#define FFN    4096
#define NHEAD  16
#define HDIM   64

// ---------------- fp32 scratch ----------------
__device__ float g_attnout[TOKENS * (size_t)DMODEL];
__device__ float g_h1     [TOKENS * (size_t)DMODEL];
__device__ float g_ffn2   [TOKENS * (size_t)DMODEL];

// ---------------- fp16 scratch ----------------
__device__ __half g_xh   [TOKENS * (size_t)DMODEL];
__device__ __half g_wqt_h[(size_t)D3 * DMODEL];     // [N][K]
__device__ __half g_wot_h[(size_t)DMODEL * DMODEL];
__device__ __half g_w1t_h[(size_t)FFN * DMODEL];
__device__ __half g_w2t_h[(size_t)DMODEL * FFN];
__device__ __half g_attnh[TOKENS * (size_t)DMODEL];
__device__ __half g_h1h  [TOKENS * (size_t)DMODEL];
__device__ __half g_fhh  [TOKENS * (size_t)FFN];

// ---------------- per-head planar fp16 QKV ----------
// layout: [bh][seq][64]
__device__ __half g_qph[(size_t)BATCH * NHEAD * SEQ * HDIM];
__device__ __half g_kph[(size_t)BATCH * NHEAD * SEQ * HDIM];
__device__ __half g_vph[(size_t)BATCH * NHEAD * SEQ * HDIM];

// =====================================================================
// helpers
// =====================================================================
__device__ __forceinline__ uint32_t smem_u32(const void* p) {
    uint32_t a;
    asm("{ .reg .u64 t; cvta.to.shared.u64 t, %1; cvt.u32.u64 %0, t; }"
        : "=r"(a) : "l"(p));
    return a;
}

__device__ __forceinline__ void ldm_x4(uint32_t* r, uint32_t addr) {
    asm volatile("ldmatrix.sync.aligned.m8n8.x4.shared.b16 {%0,%1,%2,%3}, [%4];"
                 : "=r"(r[0]), "=r"(r[1]), "=r"(r[2]), "=r"(r[3]) : "r"(addr));
}

__device__ __forceinline__ void ldm_x4t(uint32_t* r, uint32_t addr) {
    asm volatile("ldmatrix.sync.aligned.m8n8.x4.trans.shared.b16 {%0,%1,%2,%3}, [%4];"
                 : "=r"(r[0]), "=r"(r[1]), "=r"(r[2]), "=r"(r[3]) : "r"(addr));
}

// fp32-accumulate MMA (proven fastest on sm_103 classic path)
__device__ __forceinline__ void mma_f16(float* d, const uint32_t* a,
                                        uint32_t b0, uint32_t b1) {
    asm volatile(
        "mma.sync.aligned.m16n8k16.row.col.f32.f16.f16.f32 "
        "{%0,%1,%2,%3},{%4,%5,%6,%7},{%8,%9},{%0,%1,%2,%3};"
        : "+f"(d[0]), "+f"(d[1]), "+f"(d[2]), "+f"(d[3])
        : "r"(a[0]), "r"(a[1]), "r"(a[2]), "r"(a[3]), "r"(b0), "r"(b1));
}

__device__ __forceinline__ uint32_t packh2(float a, float b) {
    __half2 h = __floats2half2_rn(a, b);
    return *reinterpret_cast<uint32_t*>(&h);
}

__device__ __forceinline__ void cp16(uint32_t dst, const void* src) {
    asm volatile("cp.async.cg.shared.global [%0], [%1], 16;"
                 :: "r"(dst), "l"(src));
}
#define CP_COMMIT() asm volatile("cp.async.commit_group;" ::: "memory")
#define CP_WAIT0()  asm volatile("cp.async.wait_group 0;" ::: "memory")

// fused QKV epilogue writer: (row, col pair) of qkv fp32 -> planar fp16
__device__ __forceinline__ void qkv_write(
    __half* __restrict__ qh, __half* __restrict__ kh, __half* __restrict__ vh,
    int row, int col, float x, float y)
{
    const int h    = col / 192;
    const int r2   = col - h * 192;
    const int part = r2 >> 6;            // 0=q 1=k 2=v
    const int d    = r2 & 63;            // even (col pairs are even)
    const int b    = row >> 11, s = row & 2047;
    const size_t po = ((size_t)(b * NHEAD + h) * SEQ + s) * HDIM + d;
    if (part == 0) {
        *(uint32_t*)(qh + po) = packh2(x * 0.125f, y * 0.125f);
    } else if (part == 1) {
        *(uint32_t*)(kh + po) = packh2(x, y);
    } else {
        *(uint32_t*)(vh + po) = packh2(x, y);
    }
}

// =====================================================================
// convert kernels (run once per launch; memory-bound)
// =====================================================================
__global__ __launch_bounds__(256)
void conv_plain(const float* __restrict__ src, __half* __restrict__ dh)
{
    const int idx = blockIdx.x * 256 + threadIdx.x;     // float4 index
    float4 v = ((const float4*)src)[idx];
    ((uint2*)dh)[idx] = make_uint2(packh2(v.x, v.y), packh2(v.z, v.w));
}

// Batched weight transpose+convert: all four W[K][N] -> Th[N][K] in ONE launch.
#define CT_WQ_END 3072
#define CT_WO_END (CT_WQ_END + 1024)
#define CT_W1_END (CT_WO_END + 4096)
#define CT_TOTAL  (CT_W1_END + 4096)

__global__ __launch_bounds__(256)
void conv_transpose_all(const float* __restrict__ Wq, __half* __restrict__ Tq,
                        const float* __restrict__ Wo, __half* __restrict__ To,
                        const float* __restrict__ W1, __half* __restrict__ T1,
                        const float* __restrict__ W2, __half* __restrict__ T2)
{
    const float* W; __half* Th; int K, N, bid;
    if (blockIdx.x < CT_WQ_END)      { W = Wq; Th = Tq; K = DMODEL; N = D3;
                                       bid = blockIdx.x; }
    else if (blockIdx.x < CT_WO_END) { W = Wo; Th = To; K = DMODEL; N = DMODEL;
                                       bid = blockIdx.x - CT_WQ_END; }
    else if (blockIdx.x < CT_W1_END) { W = W1; Th = T1; K = DMODEL; N = FFN;
                                       bid = blockIdx.x - CT_WO_END; }
    else                             { W = W2; Th = T2; K = FFN;    N = DMODEL;
                                       bid = blockIdx.x - CT_W1_END; }
    const int ntx = N >> 5;                    // tiles along N
    const int bn  = (bid % ntx) * 32;
    const int bk  = (bid / ntx) * 32;

    __shared__ float t[32][33];
    const int tx = threadIdx.x & 31, ty = threadIdx.x >> 5;   // 32 x 8
    #pragma unroll
    for (int j = 0; j < 32; j += 8)
        t[ty + j][tx] = W[(size_t)(bk + ty + j) * N + bn + tx];
    __syncthreads();
    const int u  = threadIdx.x & 15;          // k-pair 0..15
    const int n0 = threadIdx.x >> 4;          // 0..15
    #pragma unroll
    for (int j = 0; j < 2; ++j) {
        const int n = n0 + j * 16;
        const float v0 = t[2 * u][n];
        const float v1 = t[2 * u + 1][n];
        *(uint32_t*)(Th + (size_t)(bn + n) * K + bk + 2 * u) = packh2(v0, v1);
    }
}

// =====================================================================
// HMMA GEMM, pure fp16, f32 accumulate (proven config):
// C = A @ B^T + bias.   A: [M][K] fp16.  B: [N][K] fp16.
// CTA 128x128, BK=64 (2x 32-k sub-tiles), 8 warps (warp tile 64x32),
// cp.async double buffer, 2 CTAs/SM.
// MODE: 0 = fp32 out, 1 = relu + fp16 out, 2 = fused QKV planar out.
// =====================================================================
#define STRB   80                     // bytes per smem row (32 fp16 + pad)
#define TILE32 (128 * STRB)           // 10240 B per 128x32 tile
#define BUF_B  (4 * TILE32)           // A0, A1, B0, B1 = 40960 B
#define GEMM_SMEM (2 * BUF_B)         // 81920 B

template<int MODE>
__global__ __launch_bounds__(256, 2)
void gemm_f16(const __half* __restrict__ Ah,
              const __half* __restrict__ Bh,
              const float* __restrict__ bias,
              float* __restrict__ C,
              __half* __restrict__ Ch,
              __half* __restrict__ qh, __half* __restrict__ kh,
              __half* __restrict__ vh,
              int M, int N, int K)
{
    extern __shared__ char smraw[];
    const uint32_t sb = smem_u32(smraw);
    const int tid = threadIdx.x;
    const int l   = tid & 31, w = tid >> 5;
    const int bm  = blockIdx.y * 128, bn = blockIdx.x * 128;
    const int wm  = (w & 1) << 6;
    const int wn  = (w >> 1) << 5;

    const int la = l & 15;
    const int lk = (l >> 4) << 3;
    const int T  = K >> 6;

    float acc[4][4][4];
    #pragma unroll
    for (int i = 0; i < 4; ++i)
        #pragma unroll
        for (int j = 0; j < 4; ++j)
            #pragma unroll
            for (int q = 0; q < 4; ++q) acc[i][j][q] = 0.f;

    auto issue_tile = [&](int t) {
        const int k0 = t << 6;
        const uint32_t base = sb + (t & 1) * BUF_B;
        #pragma unroll
        for (int s32 = 0; s32 < 2; ++s32)
            #pragma unroll
            for (int i = 0; i < 2; ++i) {
                const int c   = tid + (i << 8);     // 0..511
                const int row = c >> 2, kc = c & 3;
                const uint32_t doff = (uint32_t)(row * STRB + kc * 16);
                const int kg = k0 + s32 * 32 + kc * 8;
                cp16(base + s32 * TILE32 + doff,
                     Ah + (size_t)(bm + row) * K + kg);
                cp16(base + 2 * TILE32 + s32 * TILE32 + doff,
                     Bh + (size_t)(bn + row) * K + kg);
            }
        CP_COMMIT();
    };

    auto compute = [&](int bsel) {
        const uint32_t base0 = sb + bsel * BUF_B;
        #pragma unroll
        for (int s32 = 0; s32 < 2; ++s32) {
            const uint32_t baseA = base0 + s32 * TILE32;
            const uint32_t baseB = base0 + 2 * TILE32 + s32 * TILE32;
            #pragma unroll
            for (int ks = 0; ks < 2; ++ks) {
                uint32_t ah[4][4], bh[2][4];
                #pragma unroll
                for (int mf = 0; mf < 4; ++mf) {
                    uint32_t off = (uint32_t)((wm + mf * 16 + la) * STRB +
                                              (ks * 16 + lk) * 2);
                    ldm_x4(ah[mf], baseA + off);
                }
                #pragma unroll
                for (int nf2 = 0; nf2 < 2; ++nf2) {
                    uint32_t off = (uint32_t)((wn + nf2 * 16 + la) * STRB +
                                              (ks * 16 + lk) * 2);
                    ldm_x4(bh[nf2], baseB + off);
                }
                #pragma unroll
                for (int mf = 0; mf < 4; ++mf)
                    #pragma unroll
                    for (int nf = 0; nf < 4; ++nf) {
                        const int g = nf >> 1, s = nf & 1;
                        mma_f16(acc[mf][nf], ah[mf], bh[g][s], bh[g][2 + s]);
                    }
            }
        }
    };

    issue_tile(0);
    for (int t = 0; t < T; ++t) {
        CP_WAIT0();
        __syncthreads();
        if (t + 1 < T) issue_tile(t + 1);
        compute(t & 1);
        __syncthreads();
    }

    const int g  = l >> 2;
    const int tg = (l & 3) << 1;
    #pragma unroll
    for (int mf = 0; mf < 4; ++mf) {
        const int r0 = bm + wm + mf * 16 + g;
        #pragma unroll
        for (int nf = 0; nf < 4; ++nf) {
            const int c = bn + wn + nf * 8 + tg;
            float2 bv = *(const float2*)&bias[c];
            float v0 = acc[mf][nf][0] + bv.x;
            float v1 = acc[mf][nf][1] + bv.y;
            float v2 = acc[mf][nf][2] + bv.x;
            float v3 = acc[mf][nf][3] + bv.y;
            if (MODE == 1) {
                v0 = fmaxf(v0, 0.f); v1 = fmaxf(v1, 0.f);
                v2 = fmaxf(v2, 0.f); v3 = fmaxf(v3, 0.f);
                *(uint32_t*)((char*)Ch + ((size_t)r0 * N + c) * 2)       = packh2(v0, v1);
                *(uint32_t*)((char*)Ch + ((size_t)(r0 + 8) * N + c) * 2) = packh2(v2, v3);
            } else if (MODE == 2) {
                qkv_write(qh, kh, vh, r0,     c, v0, v1);
                qkv_write(qh, kh, vh, r0 + 8, c, v2, v3);
            } else {
                *(float2*)&C[(size_t)r0 * N + c]       = make_float2(v0, v1);
                *(float2*)&C[(size_t)(r0 + 8) * N + c] = make_float2(v2, v3);
            }
        }
    }
}

// =====================================================================
// MMA flash attention, K-tile 64 (was 128): sacc halves to 32 regs so
// launch_bounds(256,2) fits 2 CTAs/SM (occupancy 12.5% -> 25%).
// grid (16 qtiles, 32 bh), 256 threads (8 warps), warp = 16 q-rows.
// =====================================================================
#define A_STR    72                        // halves per smem row (64 + 8 pad)
#define AQ_TILE  (128 * A_STR)             // Q tile: 128 rows = 9216 halves
#define AKV_TILE (64 * A_STR)              // K/V tile: 64 rows = 4608 halves
#define A_QH     0
#define A_BUF0   AQ_TILE
#define A_BUFSZ  (2 * AKV_TILE)            // Kh + Vh = 9216 halves
#define A_KH     0
#define A_VH     AKV_TILE
#define ATTN_SMEM ((A_BUF0 + 2 * A_BUFSZ) * 2)   // 55296 bytes

__global__ __launch_bounds__(256, 2)
void attention_mma(const __half* __restrict__ qh_g,
                   const __half* __restrict__ kh_g, const __half* __restrict__ vh_g,
                   __half* __restrict__ outh)
{
    extern __shared__ char smraw[];
    const uint32_t sb = smem_u32(smraw);
    const int tid = threadIdx.x;
    const int l   = tid & 31, w = tid >> 5;
    const int qt  = blockIdx.x;
    const int bh  = blockIdx.y;
    const int b   = bh >> 4, h = bh & 15;

    const size_t plane = (size_t)bh * SEQ * HDIM;
    const int la  = l & 15;
    const int lk8 = (l >> 4) << 3;
    const int qrow0 = w << 4;

    // rows128: Q tile (128 rows, 4 iters); K/V tiles (64 rows, 2 iters)
    auto load_q = [&](const __half* src, int row0) {
        #pragma unroll
        for (int i = 0; i < 4; ++i) {
            const int c   = tid + (i << 8);        // 0..1023
            const int row = c >> 3, c8 = (c & 7) << 3;
            cp16(sb + (A_QH + row * A_STR + c8) * 2,
                 src + plane + (size_t)(row0 + row) * HDIM + c8);
        }
    };
    auto load_kv = [&](const __half* src, uint32_t dsth, int row0) {
        #pragma unroll
        for (int i = 0; i < 2; ++i) {
            const int c   = tid + (i << 8);        // 0..511
            const int row = c >> 3, c8 = (c & 7) << 3;
            cp16(sb + (dsth + row * A_STR + c8) * 2,
                 src + plane + (size_t)(row0 + row) * HDIM + c8);
        }
    };

    load_q(qh_g, qt * 128);
    load_kv(kh_g, A_BUF0 + A_KH, 0);
    load_kv(vh_g, A_BUF0 + A_VH, 0);
    CP_COMMIT();

    float oacc[8][4];
    #pragma unroll
    for (int i = 0; i < 8; ++i)
        #pragma unroll
        for (int j = 0; j < 4; ++j) oacc[i][j] = 0.f;
    float mrow0 = -1e30f, mrow1 = -1e30f, lrow0 = 0.f, lrow1 = 0.f;

    for (int kt = 0; kt < SEQ / 64; ++kt) {
        CP_WAIT0();
        __syncthreads();
        if (kt + 1 < SEQ / 64) {
            const uint32_t nb = A_BUF0 + ((kt + 1) & 1) * A_BUFSZ;
            load_kv(kh_g, nb + A_KH, (kt + 1) * 64);
            load_kv(vh_g, nb + A_VH, (kt + 1) * 64);
            CP_COMMIT();
        }
        const uint32_t kb_base = sb + (A_BUF0 + (kt & 1) * A_BUFSZ) * 2;

        // ---- S = Q K^T (64 cols) ----
        float sacc[8][4];
        #pragma unroll
        for (int i = 0; i < 8; ++i)
            #pragma unroll
            for (int j = 0; j < 4; ++j) sacc[i][j] = 0.f;

        #pragma unroll
        for (int ks = 0; ks < 4; ++ks) {
            const uint32_t qoff = (uint32_t)((qrow0 + la) * A_STR + ks * 16 + lk8) * 2;
            uint32_t qhf[4];
            ldm_x4(qhf, sb + A_QH * 2 + qoff);
            uint32_t kb[4][4];
            #pragma unroll
            for (int g2 = 0; g2 < 4; ++g2)
                ldm_x4(kb[g2], kb_base +
                       (uint32_t)(((g2 << 4) + la) * A_STR + ks * 16 + lk8) * 2);
            #pragma unroll
            for (int nf = 0; nf < 8; ++nf) {
                const int g2 = nf >> 1, s = nf & 1;
                mma_f16(sacc[nf], qhf, kb[g2][s], kb[g2][2 + s]);
            }
        }

        // ---- online softmax ----
        float tm0 = -1e30f, tm1 = -1e30f;
        #pragma unroll
        for (int nf = 0; nf < 8; ++nf) {
            tm0 = fmaxf(tm0, fmaxf(sacc[nf][0], sacc[nf][1]));
            tm1 = fmaxf(tm1, fmaxf(sacc[nf][2], sacc[nf][3]));
        }
        tm0 = fmaxf(tm0, __shfl_xor_sync(0xffffffffu, tm0, 1));
        tm0 = fmaxf(tm0, __shfl_xor_sync(0xffffffffu, tm0, 2));
        tm1 = fmaxf(tm1, __shfl_xor_sync(0xffffffffu, tm1, 1));
        tm1 = fmaxf(tm1, __shfl_xor_sync(0xffffffffu, tm1, 2));
        const float m0n = fmaxf(mrow0, tm0), m1n = fmaxf(mrow1, tm1);
        const float c0 = __expf(mrow0 - m0n), c1 = __expf(mrow1 - m1n);
        float rs0 = 0.f, rs1 = 0.f;
        #pragma unroll
        for (int nf = 0; nf < 8; ++nf) {
            sacc[nf][0] = __expf(sacc[nf][0] - m0n);
            sacc[nf][1] = __expf(sacc[nf][1] - m0n);
            sacc[nf][2] = __expf(sacc[nf][2] - m1n);
            sacc[nf][3] = __expf(sacc[nf][3] - m1n);
            rs0 += sacc[nf][0] + sacc[nf][1];
            rs1 += sacc[nf][2] + sacc[nf][3];
        }
        rs0 += __shfl_xor_sync(0xffffffffu, rs0, 1);
        rs0 += __shfl_xor_sync(0xffffffffu, rs0, 2);
        rs1 += __shfl_xor_sync(0xffffffffu, rs1, 1);
        rs1 += __shfl_xor_sync(0xffffffffu, rs1, 2);
        lrow0 = lrow0 * c0 + rs0;  mrow0 = m0n;
        lrow1 = lrow1 * c1 + rs1;  mrow1 = m1n;
        #pragma unroll
        for (int nf = 0; nf < 8; ++nf) {
            oacc[nf][0] *= c0; oacc[nf][1] *= c0;
            oacc[nf][2] *= c1; oacc[nf][3] *= c1;
        }

        // ---- O += P V (64 keys) ----
        #pragma unroll
        for (int ks2 = 0; ks2 < 4; ++ks2) {
            uint32_t aP[4];
            aP[0] = packh2(sacc[2 * ks2][0],     sacc[2 * ks2][1]);
            aP[1] = packh2(sacc[2 * ks2][2],     sacc[2 * ks2][3]);
            aP[2] = packh2(sacc[2 * ks2 + 1][0], sacc[2 * ks2 + 1][1]);
            aP[3] = packh2(sacc[2 * ks2 + 1][2], sacc[2 * ks2 + 1][3]);
            #pragma unroll
            for (int nb = 0; nb < 4; ++nb) {
                const uint32_t voff =
                    (uint32_t)(((ks2 << 4) + la) * A_STR + (nb << 4) + lk8) * 2;
                uint32_t vbh[4];
                ldm_x4t(vbh, kb_base + A_VH * 2 + voff);
                mma_f16(oacc[2 * nb],     aP, vbh[0], vbh[1]);
                mma_f16(oacc[2 * nb + 1], aP, vbh[2], vbh[3]);
            }
        }
    }

    const int g  = l >> 2;
    const int tq = (l & 3) << 1;
    const float inv0 = 1.f / lrow0, inv1 = 1.f / lrow1;
    const size_t tok0 = (size_t)b * SEQ + qt * 128 + qrow0 + g;
    #pragma unroll
    for (int nf = 0; nf < 8; ++nf) {
        const int col = h * HDIM + nf * 8 + tq;
        *(uint32_t*)((char*)outh + (tok0 * DMODEL + col) * 2) =
            packh2(oacc[nf][0] * inv0, oacc[nf][1] * inv0);
        *(uint32_t*)((char*)outh + ((tok0 + 8) * DMODEL + col) * 2) =
            packh2(oacc[nf][2] * inv1, oacc[nf][3] * inv1);
    }
}

// =====================================================================
// Fused residual add + LayerNorm; optionally emits fp16 too.
// =====================================================================
template<bool EMIT>
__global__ __launch_bounds__(256)
void add_ln_kernel(const float* __restrict__ a, const float* __restrict__ res,
                   const float* __restrict__ gamma, const float* __restrict__ beta,
                   float* __restrict__ out,
                   __half* __restrict__ outh)
{
    __shared__ float ss[8], qq[8];
    const int row = blockIdx.x;
    const int tid = threadIdx.x;
    const size_t base = (size_t)row * DMODEL + tid * 4;

    float4 va = *(const float4*)&a[base];
    float4 vr = *(const float4*)&res[base];
    float x0 = va.x + vr.x, x1 = va.y + vr.y, x2 = va.z + vr.z, x3 = va.w + vr.w;

    float s = x0 + x1 + x2 + x3;
    float q = x0 * x0 + x1 * x1 + x2 * x2 + x3 * x3;
    #pragma unroll
    for (int off = 16; off > 0; off >>= 1) {
        s += __shfl_xor_sync(0xffffffffu, s, off);
        q += __shfl_xor_sync(0xffffffffu, q, off);
    }
    const int w = tid >> 5;
    if ((tid & 31) == 0) { ss[w] = s; qq[w] = q; }
    __syncthreads();
    if (tid < 32) {
        float s2 = (tid < 8) ? ss[tid] : 0.f;
        float q2 = (tid < 8) ? qq[tid] : 0.f;
        #pragma unroll
        for (int off = 4; off > 0; off >>= 1) {
            s2 += __shfl_xor_sync(0xffffffffu, s2, off);
            q2 += __shfl_xor_sync(0xffffffffu, q2, off);
        }
        if (tid == 0) { ss[0] = s2; qq[0] = q2; }
    }
    __syncthreads();

    const float mean = ss[0] * (1.f / DMODEL);
    const float var  = qq[0] * (1.f / DMODEL) - mean * mean;
    const float rstd = rsqrtf(var + 1e-5f);

    float4 g  = *(const float4*)&gamma[tid * 4];
    float4 bt = *(const float4*)&beta[tid * 4];
    float4 ov;
    ov.x = (x0 - mean) * rstd * g.x + bt.x;
    ov.y = (x1 - mean) * rstd * g.y + bt.y;
    ov.z = (x2 - mean) * rstd * g.z + bt.z;
    ov.w = (x3 - mean) * rstd * g.w + bt.w;
    *(float4*)&out[base] = ov;

    if (EMIT) {
        *(uint2*)((char*)outh + base * 2) =
            make_uint2(packh2(ov.x, ov.y), packh2(ov.z, ov.w));
    }
}

// =====================================================================
// kernel_launch
// =====================================================================
extern "C" void kernel_launch(void* const* d_in, const int* in_sizes, int n_in,
                              void* d_out, int out_size)
{
    const float* x      = (const float*)d_in[0];
    const float* W_qkv  = (const float*)d_in[1];
    const float* b_qkv  = (const float*)d_in[2];
    const float* W_o    = (const float*)d_in[3];
    const float* b_o    = (const float*)d_in[4];
    const float* gamma1 = (const float*)d_in[5];
    const float* beta1  = (const float*)d_in[6];
    const float* W1     = (const float*)d_in[7];
    const float* b1     = (const float*)d_in[8];
    const float* W2     = (const float*)d_in[9];
    const float* b2     = (const float*)d_in[10];
    const float* gamma2 = (const float*)d_in[11];
    const float* beta2  = (const float*)d_in[12];
    float* out = (float*)d_out;

    float *attnout, *h1, *ffn2;
    cudaGetSymbolAddress((void**)&attnout, g_attnout);
    cudaGetSymbolAddress((void**)&h1,      g_h1);
    cudaGetSymbolAddress((void**)&ffn2,    g_ffn2);

    __half *xh, *wqh, *woh, *w1h, *w2h;
    __half *ath, *h1h, *fhh;
    __half *qph, *kph, *vph;
    cudaGetSymbolAddress((void**)&xh,  g_xh);
    cudaGetSymbolAddress((void**)&wqh, g_wqt_h);
    cudaGetSymbolAddress((void**)&woh, g_wot_h);
    cudaGetSymbolAddress((void**)&w1h, g_w1t_h);
    cudaGetSymbolAddress((void**)&w2h, g_w2t_h);
    cudaGetSymbolAddress((void**)&ath, g_attnh);
    cudaGetSymbolAddress((void**)&h1h, g_h1h);
    cudaGetSymbolAddress((void**)&fhh, g_fhh);
    cudaGetSymbolAddress((void**)&qph, g_qph);
    cudaGetSymbolAddress((void**)&kph, g_kph);
    cudaGetSymbolAddress((void**)&vph, g_vph);

    cudaFuncSetAttribute(attention_mma,
                         cudaFuncAttributeMaxDynamicSharedMemorySize, ATTN_SMEM);
    cudaFuncSetAttribute(gemm_f16<0>,
                         cudaFuncAttributeMaxDynamicSharedMemorySize, GEMM_SMEM);
    cudaFuncSetAttribute(gemm_f16<1>,
                         cudaFuncAttributeMaxDynamicSharedMemorySize, GEMM_SMEM);
    cudaFuncSetAttribute(gemm_f16<2>,
                         cudaFuncAttributeMaxDynamicSharedMemorySize, GEMM_SMEM);

    dim3 blk(256);

    // ---- one-time converts (x + all four weights in one launch) ----
    conv_plain<<<(TOKENS * DMODEL) / (256 * 4), blk>>>(x, xh);
    conv_transpose_all<<<CT_TOTAL, blk>>>(W_qkv, wqh, W_o, woh,
                                          W1, w1h, W2, w2h);

    // 1) qkv GEMM with fused planar-QKV epilogue       [4096, 3072]
    gemm_f16<2><<<dim3(D3 / 128, TOKENS / 128), blk, GEMM_SMEM>>>(
        xh, wqh, b_qkv, nullptr, nullptr,
        qph, kph, vph, TOKENS, D3, DMODEL);

    // 2) MMA flash attention -> fp16                   [4096, 1024]
    attention_mma<<<dim3(SEQ / 128, BATCH * NHEAD), blk, ATTN_SMEM>>>(
        qph, kph, vph, ath);

    // 3) attn_out = attn @ W_o + b_o                   [4096, 1024]
    gemm_f16<0><<<dim3(DMODEL / 128, TOKENS / 128), blk, GEMM_SMEM>>>(
        ath, woh, b_o, attnout, nullptr,
        nullptr, nullptr, nullptr, TOKENS, DMODEL, DMODEL);

    // 4) h1 = LN(attn_out + x)  (+ fp16)
    add_ln_kernel<true><<<TOKENS, blk>>>(attnout, x, gamma1, beta1, h1, h1h);

    // 5) ffnh = relu(h1 @ W1 + b1) -> fp16             [4096, 4096]
    gemm_f16<1><<<dim3(FFN / 128, TOKENS / 128), blk, GEMM_SMEM>>>(
        h1h, w1h, b1, nullptr, fhh,
        nullptr, nullptr, nullptr, TOKENS, FFN, DMODEL);

    // 6) ffn2 = ffnh @ W2 + b2                         [4096, 1024]
    gemm_f16<0><<<dim3(DMODEL / 128, TOKENS / 128), blk, GEMM_SMEM>>>(
        fhh, w2h, b2, ffn2, nullptr,
        nullptr, nullptr, nullptr, TOKENS, DMODEL, FFN);

    // 7) out = LN(ffn2 + h1)
    add_ln_kernel<false><<<TOKENS, blk>>>(ffn2, h1, gamma2, beta2, out, nullptr);
}